// round 2
// baseline (speedup 1.0000x reference)
#include <cuda_runtime.h>
#include <math.h>

// LinearTimeMMDLoss — single fused kernel.
// pairs i in [0, m/2): xo=src[2i], xe=src[2i+1], yo=tgt[2i], ye=tgt[2i+1]
// dxx=|xo-xe|^2 etc over d=512; bw=(sum)/4/4; b_k=bw*2^k+1e-6
// h_i = sum_k exp(-dxx/b_k)+exp(-dyy/b_k)-exp(-dxy/b_k)-exp(-dyx/b_k)
// out = mean_i h_i

#define D 512
#define D4 (D / 4)                 // 128 float4 per row
#define WARPS_PER_BLOCK 8
#define THREADS (WARPS_PER_BLOCK * 32)
#define PAIRS_PER_WARP 4
#define PAIRS_PER_BLOCK (WARPS_PER_BLOCK * PAIRS_PER_WARP)   // 32
#define MAX_BLOCKS 4096

__device__ double g_block_partials[MAX_BLOCKS];
__device__ int    g_done_counter = 0;   // reset to 0 by last block each call

__global__ void __launch_bounds__(THREADS) mmd_fused_kernel(
    const float* __restrict__ source,
    const float* __restrict__ target,
    float* __restrict__ out,
    int m2, int num_blocks)
{
    const int warp_id = threadIdx.x >> 5;
    const int lane    = threadIdx.x & 31;
    const int warp_g  = blockIdx.x * WARPS_PER_BLOCK + warp_id;

    double h_acc = 0.0;

    #pragma unroll
    for (int p = 0; p < PAIRS_PER_WARP; p++) {
        const int pair = warp_g * PAIRS_PER_WARP + p;
        if (pair >= m2) break;

        const float4* xo = (const float4*)(source + (size_t)(2 * pair)     * D);
        const float4* xe = (const float4*)(source + (size_t)(2 * pair + 1) * D);
        const float4* yo = (const float4*)(target + (size_t)(2 * pair)     * D);
        const float4* ye = (const float4*)(target + (size_t)(2 * pair + 1) * D);

        // Front-batch ALL 16 independent float4 loads (MLP_p1 = 16)
        float4 A[4], B[4], C[4], E[4];
        #pragma unroll
        for (int k = 0; k < 4; k++) A[k] = xo[lane + 32 * k];
        #pragma unroll
        for (int k = 0; k < 4; k++) B[k] = xe[lane + 32 * k];
        #pragma unroll
        for (int k = 0; k < 4; k++) C[k] = yo[lane + 32 * k];
        #pragma unroll
        for (int k = 0; k < 4; k++) E[k] = ye[lane + 32 * k];

        float dxx = 0.f, dyy = 0.f, dxy = 0.f, dyx = 0.f;
        #pragma unroll
        for (int k = 0; k < 4; k++) {
            float t;
            t = A[k].x - B[k].x; dxx = fmaf(t, t, dxx);
            t = A[k].y - B[k].y; dxx = fmaf(t, t, dxx);
            t = A[k].z - B[k].z; dxx = fmaf(t, t, dxx);
            t = A[k].w - B[k].w; dxx = fmaf(t, t, dxx);

            t = C[k].x - E[k].x; dyy = fmaf(t, t, dyy);
            t = C[k].y - E[k].y; dyy = fmaf(t, t, dyy);
            t = C[k].z - E[k].z; dyy = fmaf(t, t, dyy);
            t = C[k].w - E[k].w; dyy = fmaf(t, t, dyy);

            t = A[k].x - E[k].x; dxy = fmaf(t, t, dxy);
            t = A[k].y - E[k].y; dxy = fmaf(t, t, dxy);
            t = A[k].z - E[k].z; dxy = fmaf(t, t, dxy);
            t = A[k].w - E[k].w; dxy = fmaf(t, t, dxy);

            t = B[k].x - C[k].x; dyx = fmaf(t, t, dyx);
            t = B[k].y - C[k].y; dyx = fmaf(t, t, dyx);
            t = B[k].z - C[k].z; dyx = fmaf(t, t, dyx);
            t = B[k].w - C[k].w; dyx = fmaf(t, t, dyx);
        }

        // warp tree-reduce the four sums (deterministic)
        #pragma unroll
        for (int off = 16; off > 0; off >>= 1) {
            dxx += __shfl_xor_sync(0xffffffffu, dxx, off);
            dyy += __shfl_xor_sync(0xffffffffu, dyy, off);
            dxy += __shfl_xor_sync(0xffffffffu, dxy, off);
            dyx += __shfl_xor_sync(0xffffffffu, dyx, off);
        }

        if (lane == 0) {
            float bw = (dxx + dyy + dxy + dyx) * (0.25f * 0.25f);
            float mult = 1.0f;
            #pragma unroll
            for (int k = 0; k < 5; k++) {
                float b  = bw * mult + 1e-6f;
                float ib = 1.0f / b;
                h_acc += (double)expf(-dxx * ib) + (double)expf(-dyy * ib)
                       - (double)expf(-dxy * ib) - (double)expf(-dyx * ib);
                mult *= 2.0f;
            }
        }
    }

    // block reduce (lane 0 of each warp holds its warp's h sum)
    __shared__ double s_h[WARPS_PER_BLOCK];
    if (lane == 0) s_h[warp_id] = h_acc;
    __syncthreads();

    __shared__ bool s_is_last;
    if (threadIdx.x == 0) {
        double sum = 0.0;
        #pragma unroll
        for (int w = 0; w < WARPS_PER_BLOCK; w++) sum += s_h[w];
        g_block_partials[blockIdx.x] = sum;
        __threadfence();
        int prev = atomicAdd(&g_done_counter, 1);
        s_is_last = (prev == num_blocks - 1);
    }
    __syncthreads();

    if (s_is_last) {
        // last block: deterministic reduce of all partials
        __shared__ double s_r[THREADS];
        double v = 0.0;
        for (int i = threadIdx.x; i < num_blocks; i += THREADS)
            v += g_block_partials[i];
        s_r[threadIdx.x] = v;
        __syncthreads();
        #pragma unroll
        for (int off = THREADS / 2; off > 0; off >>= 1) {
            if (threadIdx.x < off) s_r[threadIdx.x] += s_r[threadIdx.x + off];
            __syncthreads();
        }
        if (threadIdx.x == 0) {
            out[0] = (float)(s_r[0] / (double)m2);
            g_done_counter = 0;   // reset for next graph replay
            __threadfence();
        }
    }
}

extern "C" void kernel_launch(void* const* d_in, const int* in_sizes, int n_in,
                              void* d_out, int out_size)
{
    const float* source = (const float*)d_in[0];
    const float* target = (const float*)d_in[1];
    float* out = (float*)d_out;

    const int m  = in_sizes[0] / D;   // 65536
    const int m2 = m / 2;             // 32768

    int blocks = (m2 + PAIRS_PER_BLOCK - 1) / PAIRS_PER_BLOCK;  // 1024
    if (blocks > MAX_BLOCKS) blocks = MAX_BLOCKS;

    mmd_fused_kernel<<<blocks, THREADS>>>(source, target, out, m2, blocks);
}